// round 13
// baseline (speedup 1.0000x reference)
#include <cuda_runtime.h>
#include <cstdint>

// Gent hyperelastic energy over N 3x3 deformation gradients (elementwise).
//   I1 = ||F||_F^2 ; J = det(F) ; I1bar = I1 * J^(-2/3)
//   vol = (J^2-1)/2 - ln J ;  w = A*ln(1 - (I1bar-3)/JM) + B*vol^4
//   A = -(G/2)*JM = -1442307.6923..., B = K/2 = 31250, JM = 100.
//
// Direct-LDG structure (no smem / no barriers / no TMA):
//   Each thread owns 4 CONSECUTIVE matrices = 144 contiguous bytes
//   = 9 aligned float4 loads issued back-to-back (MLP=9), then computes
//   4 energies and writes ONE float4 (4 consecutive outputs, coalesced).
//   Warp-local line reuse: a warp's 9 scattered LDG.128 touch 36 lines,
//   all of which belong to the warp's own 4.5 KB span — L1 serves repeats,
//   sector traffic is exact.
// Math: one MUFU.LG2 feeds ln(J) and J^(-2/3); ln(1-u) via 5-term series.
// Output via streaming store (st.global.cs).

#define THREADS 256
#define MPT 4   // matrices per thread, consecutive

__device__ __forceinline__ float gent_energy(
    float a00, float a01, float a02,
    float a10, float a11, float a12,
    float a20, float a21, float a22)
{
    const float A = -1442307.6923076923f;   // -(G/2)*JM
    const float B = 31250.0f;               // K/2
    const float JM_inv = 0.01f;
    const float LN2 = 0.69314718055994531f;

    float I1 = a00*a00 + a01*a01 + a02*a02
             + a10*a10 + a11*a11 + a12*a12
             + a20*a20 + a21*a21 + a22*a22;

    float J = a00*(a11*a22 - a12*a21)
            - a01*(a10*a22 - a12*a20)
            + a02*(a10*a21 - a11*a20);

    // One LG2 feeds both ln(J) and J^(-2/3).
    float l2 = __log2f(J);
    float lnJ = l2 * LN2;
    float Jm23 = exp2f(-0.66666666666666667f * l2);

    float I1bar = I1 * Jm23;

    float vol = fmaf(0.5f, J*J, -0.5f) - lnJ;
    float vol2 = vol * vol;
    float vol4 = vol2 * vol2;

    // ln(1-u) = -(u + u^2/2 + u^3/3 + u^4/4 + u^5/5)
    float u = (I1bar - 3.0f) * JM_inv;
    float p = fmaf(u, 0.2f, 0.25f);
    p = fmaf(u, p, 0.33333333333333333f);
    p = fmaf(u, p, 0.5f);
    p = fmaf(u, p, 1.0f);
    float ln1mu = -u * p;

    return fmaf(B, vol4, A * ln1mu);
}

__global__ __launch_bounds__(THREADS)
void gent_kernel(const float* __restrict__ x, float* __restrict__ w, int n)
{
    const long long t = (long long)blockIdx.x * THREADS + threadIdx.x;
    const long long mat0 = t * MPT;
    if (mat0 >= n) return;

    // 9 back-to-back independent float4 loads: 144 contiguous bytes.
    const float4* x4 = reinterpret_cast<const float4*>(x) + t * 9;
    float4 v0 = __ldg(&x4[0]);
    float4 v1 = __ldg(&x4[1]);
    float4 v2 = __ldg(&x4[2]);
    float4 v3 = __ldg(&x4[3]);
    float4 v4 = __ldg(&x4[4]);
    float4 v5 = __ldg(&x4[5]);
    float4 v6 = __ldg(&x4[6]);
    float4 v7 = __ldg(&x4[7]);
    float4 v8 = __ldg(&x4[8]);

    // Matrix 0: floats 0..8
    float w0 = gent_energy(v0.x, v0.y, v0.z,
                           v0.w, v1.x, v1.y,
                           v1.z, v1.w, v2.x);
    // Matrix 1: floats 9..17
    float w1 = gent_energy(v2.y, v2.z, v2.w,
                           v3.x, v3.y, v3.z,
                           v3.w, v4.x, v4.y);
    // Matrix 2: floats 18..26
    float w2 = gent_energy(v4.z, v4.w, v5.x,
                           v5.y, v5.z, v5.w,
                           v6.x, v6.y, v6.z);
    // Matrix 3: floats 27..35
    float w3 = gent_energy(v6.w, v7.x, v7.y,
                           v7.z, v7.w, v8.x,
                           v8.y, v8.z, v8.w);

    // One coalesced 16B streaming store (n is a multiple of 4).
    float4 out = make_float4(w0, w1, w2, w3);
    __stcs(reinterpret_cast<float4*>(w) + t, out);
}

extern "C" void kernel_launch(void* const* d_in, const int* in_sizes, int n_in,
                              void* d_out, int out_size)
{
    const float* x = (const float*)d_in[0];
    float* w = (float*)d_out;
    const int n = out_size;                       // 4,000,000 (multiple of 4)
    const long long nthreads = (long long)n / MPT;      // 1,000,000
    const int blocks = (int)((nthreads + THREADS - 1) / THREADS);  // 3907
    gent_kernel<<<blocks, THREADS>>>(x, w, n);
}

// round 17
// speedup vs baseline: 1.2796x; 1.2796x over previous
#include <cuda_runtime.h>
#include <cstdint>

// Gent hyperelastic energy over N 3x3 deformation gradients (elementwise).
//   I1 = ||F||_F^2 ; J = det(F) ; I1bar = I1 * J^(-2/3)
//   vol = (J^2-1)/2 - ln J ;  w = A*ln(1 - (I1bar-3)/JM) + B*vol^4
//   A = -(G/2)*JM = -1442307.6923..., B = K/2 = 31250, JM = 100.
//
// Config: dur-optimal grid (15625) + max CTA-level fetch concurrency.
//   64 threads/CTA, 256 matrices/CTA = 9 KB smem -> ~25 CTAs/SM
//   (smem-capped at 225/228 KB), ~25 independent TMA fetches per SM.
//   Whole tile fetched by ONE cp.async.bulk + mbarrier; zero per-element
//   load instructions. Grid exact for N=4M (no tail).
// Math: one MUFU.LG2 feeds ln(J) and J^(-2/3); ln(1-u) via 5-term series.
// Output: streaming scalar stores, coalesced (64 consecutive floats/warp-pair).

#define THREADS 64
#define MPT 4
#define TILE_MATS (THREADS * MPT)            // 256
#define TILE_F (TILE_MATS * 9)               // 2304 floats
#define TILE_BYTES (TILE_F * 4)              // 9216 bytes

__global__ __launch_bounds__(THREADS)
void gent_kernel(const float* __restrict__ x, float* __restrict__ w, int n)
{
    __shared__ alignas(128) float sx[TILE_F];
    __shared__ alignas(8) uint64_t mbar;

    const int tid = threadIdx.x;
    const size_t total_bytes = (size_t)n * 36u;
    const size_t base_bytes = (size_t)blockIdx.x * TILE_BYTES;

    uint32_t smem_dst = (uint32_t)__cvta_generic_to_shared(sx);
    uint32_t mbar_a = (uint32_t)__cvta_generic_to_shared(&mbar);

    if (tid == 0) {
        asm volatile("mbarrier.init.shared::cta.b64 [%0], 1;" :: "r"(mbar_a) : "memory");
    }
    __syncthreads();

    if (tid == 0) {
        size_t rem = total_bytes - base_bytes;
        uint32_t bytes = rem < (size_t)TILE_BYTES ? (uint32_t)rem : (uint32_t)TILE_BYTES;
        const char* gsrc = reinterpret_cast<const char*>(x) + base_bytes;
        asm volatile("mbarrier.arrive.expect_tx.shared::cta.b64 _, [%0], %1;"
                     :: "r"(mbar_a), "r"(bytes) : "memory");
        asm volatile("cp.async.bulk.shared::cta.global.mbarrier::complete_tx::bytes "
                     "[%0], [%1], %2, [%3];"
                     :: "r"(smem_dst), "l"(gsrc), "r"(bytes), "r"(mbar_a) : "memory");
    }

    // All threads wait for the bulk copy (phase 0).
    asm volatile(
        "{\n\t"
        ".reg .pred P;\n\t"
        "LAB_WAIT_%=:\n\t"
        "mbarrier.try_wait.parity.shared::cta.b64 P, [%0], 0, 0x989680;\n\t"
        "@P bra LAB_DONE_%=;\n\t"
        "bra LAB_WAIT_%=;\n\t"
        "LAB_DONE_%=:\n\t"
        "}"
        :: "r"(mbar_a) : "memory");

    const float A = -1442307.6923076923f;   // -(G/2)*JM
    const float B = 31250.0f;               // K/2
    const float JM_inv = 0.01f;
    const float LN2 = 0.69314718055994531f;

    const long long mat_base = (long long)blockIdx.x * TILE_MATS;

    #pragma unroll
    for (int m = 0; m < MPT; m++) {
        const int local = tid + m * THREADS;     // strided: conflict-free smem
        const long long gi = mat_base + local;
        if (gi < n) {
            const float* mm = &sx[local * 9];
            float a00 = mm[0], a01 = mm[1], a02 = mm[2];
            float a10 = mm[3], a11 = mm[4], a12 = mm[5];
            float a20 = mm[6], a21 = mm[7], a22 = mm[8];

            float I1 = a00*a00 + a01*a01 + a02*a02
                     + a10*a10 + a11*a11 + a12*a12
                     + a20*a20 + a21*a21 + a22*a22;

            float J = a00*(a11*a22 - a12*a21)
                    - a01*(a10*a22 - a12*a20)
                    + a02*(a10*a21 - a11*a20);

            // One LG2 feeds both ln(J) and J^(-2/3).
            float l2 = __log2f(J);
            float lnJ = l2 * LN2;
            float Jm23 = exp2f(-0.66666666666666667f * l2);

            float I1bar = I1 * Jm23;

            float vol = fmaf(0.5f, J*J, -0.5f) - lnJ;
            float vol2 = vol * vol;
            float vol4 = vol2 * vol2;

            // ln(1-u) = -(u + u^2/2 + u^3/3 + u^4/4 + u^5/5)
            float u = (I1bar - 3.0f) * JM_inv;
            float p = fmaf(u, 0.2f, 0.25f);
            p = fmaf(u, p, 0.33333333333333333f);
            p = fmaf(u, p, 0.5f);
            p = fmaf(u, p, 1.0f);
            float ln1mu = -u * p;

            float wv = fmaf(B, vol4, A * ln1mu);
            __stcs(&w[gi], wv);   // streaming store: don't pollute L2
        }
    }
}

extern "C" void kernel_launch(void* const* d_in, const int* in_sizes, int n_in,
                              void* d_out, int out_size)
{
    const float* x = (const float*)d_in[0];
    float* w = (float*)d_out;
    const int n = out_size;  // 4,000,000
    const int blocks = (n + TILE_MATS - 1) / TILE_MATS;  // 15625 (exact)
    gent_kernel<<<blocks, THREADS>>>(x, w, n);
}